// round 11
// baseline (speedup 1.0000x reference)
#include <cuda_runtime.h>
#include <math.h>

// SimilarityTreeLSTM on GB300: dataflow (work-queue) tree evaluation in one
// persistent kernel.
//
// R11 = R7 algorithm (leaf elimination + full matvec for internal nodes,
// NO pre-leaf fold — R9/R10 proved it a net loss) with the level-synchronous
// schedule replaced by a dependency-driven work queue:
//  * per-node pending = #internal children; ready queue with valid-entry
//    protocol (init -1, push via atomicExch after threadfence)
//  * blocks claim 16 slots, process any valid subset before spinning
//    (deadlock-free: a slot's filler chain passes through lower slots)
//  * no grid barriers and no wave quantization in the compute phase
//  * ragged batches use do_group<16|8|4|1> by size

#define NNODE 65536
#define TOT   (2 * NNODE)
#define M     256
#define M3    (3 * M)
#define VOCAB 1000
#define VNB   8

// ---------------- device scratch (static: no allocations allowed) ----------
__device__ float g_hsum[TOT * M];        // children h sum
__device__ float g_fcsum[TOT * M];       // children f*c sum
__device__ float g_ioux[VOCAB * M3];     // vocab proj: emb@Wioux + bioux
__device__ float g_fxp[VOCAB * M];       // vocab proj: emb@Wfx + bfx
__device__ float g_hleaf[VOCAB * M];     // leaf h by token
__device__ float g_cleaf[VOCAB * M];     // leaf c by token
__device__ float g_hfw[VOCAB * M];       // h_leaf @ Wfh + bfh
__device__ int   g_nchild[TOT];
__device__ int   g_pend[TOT];            // remaining internal children
__device__ int   g_ready[TOT];           // work queue entries (-1 = empty)
__device__ int   g_leaf[TOT];
__device__ int   g_nleaf;
__device__ int   g_qalloc;               // next entry slot to fill
__device__ int   g_qhead;                // next slot to consume
__device__ float g_croot[2 * M];
__device__ unsigned g_barcnt;
__device__ unsigned g_sense;

__device__ __forceinline__ float sigf(float x) {
    return 1.0f / (1.0f + expf(-x));
}

// Sense-reversal grid barrier. Requires all blocks co-resident.
__device__ __forceinline__ void gsync() {
    __syncthreads();
    if (threadIdx.x == 0) {
        __threadfence();
        unsigned target = *((volatile unsigned*)&g_sense) + 1u;
        unsigned a = atomicAdd(&g_barcnt, 1u);
        if (a == gridDim.x - 1u) {
            g_barcnt = 0u;
            __threadfence();
            atomicExch(&g_sense, target);
        } else {
            while (*((volatile unsigned*)&g_sense) != target) { __nanosleep(64); }
        }
        __threadfence();
    }
    __syncthreads();
}

// Process one batch of nn (<=NT) ready internal nodes from sh_batch.
// After computing, scatter to parent and push parent if its pending hits 0.
template <int NT>
__device__ void do_group(const int* __restrict__ sh_batch, int nn,
                         const int* __restrict__ l_tok, const int* __restrict__ l_par,
                         const int* __restrict__ r_tok, const int* __restrict__ r_par,
                         const float* __restrict__ Wiouh, const float* __restrict__ Wfh,
                         float bio0, float bio1, float bio2, float bfh_t,
                         float* s_f, int* s_node, int* s_tok, int* s_parg, int* s_ptok)
{
    const int t = threadIdx.x;

    if (t < NT) {
        int node = sh_batch[(t < nn) ? t : 0];   // clamp (dup node 0)
        int tree = node >> 16, loc = node & (NNODE - 1);
        const int* tokp = tree ? r_tok : l_tok;
        const int* parp = tree ? r_par : l_par;
        int pl = parp[loc];
        s_node[t] = node;
        s_tok[t]  = tokp[loc];
        s_parg[t] = (tree << 16) + pl;
        s_ptok[t] = tokp[pl];
    }
    __syncthreads();

    // load children h sums (bypass L1: updated via L2 atomics)
    #pragma unroll
    for (int n = 0; n < NT; n++)
        s_f[n * M + t] = __ldcg(&g_hsum[s_node[n] * M + t]);
    __syncthreads();

    float a0[NT], a1[NT], a2[NT];
    #pragma unroll
    for (int n = 0; n < NT; n++) {
        int tk = s_tok[n];
        a0[n] = g_ioux[tk * M3 + t]         + bio0;
        a1[n] = g_ioux[tk * M3 + M + t]     + bio1;
        a2[n] = g_ioux[tk * M3 + 2 * M + t] + bio2;
    }

    // ---- Wiouh matvec: explicit two-phase weight double-buffer ----
    {
        float wa0[4], wa1[4], wa2[4], wb0[4], wb1[4], wb2[4];
        #pragma unroll
        for (int kk = 0; kk < 4; kk++) {
            wa0[kk] = Wiouh[kk * M3 + t];
            wa1[kk] = Wiouh[kk * M3 + M + t];
            wa2[kk] = Wiouh[kk * M3 + 2 * M + t];
        }
        #pragma unroll 1
        for (int k = 0; k < M; k += 8) {
            #pragma unroll
            for (int kk = 0; kk < 4; kk++) {
                wb0[kk] = Wiouh[(k + 4 + kk) * M3 + t];
                wb1[kk] = Wiouh[(k + 4 + kk) * M3 + M + t];
                wb2[kk] = Wiouh[(k + 4 + kk) * M3 + 2 * M + t];
            }
            #pragma unroll
            for (int n = 0; n < NT; n++) {
                const float4 h4 = *reinterpret_cast<const float4*>(s_f + n * M + k);
                a0[n] += h4.x * wa0[0]; a1[n] += h4.x * wa1[0]; a2[n] += h4.x * wa2[0];
                a0[n] += h4.y * wa0[1]; a1[n] += h4.y * wa1[1]; a2[n] += h4.y * wa2[1];
                a0[n] += h4.z * wa0[2]; a1[n] += h4.z * wa1[2]; a2[n] += h4.z * wa2[2];
                a0[n] += h4.w * wa0[3]; a1[n] += h4.w * wa1[3]; a2[n] += h4.w * wa2[3];
            }
            if (k + 8 < M) {
                #pragma unroll
                for (int kk = 0; kk < 4; kk++) {
                    wa0[kk] = Wiouh[(k + 8 + kk) * M3 + t];
                    wa1[kk] = Wiouh[(k + 8 + kk) * M3 + M + t];
                    wa2[kk] = Wiouh[(k + 8 + kk) * M3 + 2 * M + t];
                }
            }
            #pragma unroll
            for (int n = 0; n < NT; n++) {
                const float4 h4 = *reinterpret_cast<const float4*>(s_f + n * M + k + 4);
                a0[n] += h4.x * wb0[0]; a1[n] += h4.x * wb1[0]; a2[n] += h4.x * wb2[0];
                a0[n] += h4.y * wb0[1]; a1[n] += h4.y * wb1[1]; a2[n] += h4.y * wb2[1];
                a0[n] += h4.z * wb0[2]; a1[n] += h4.z * wb1[2]; a2[n] += h4.z * wb2[2];
                a0[n] += h4.w * wb0[3]; a1[n] += h4.w * wb1[3]; a2[n] += h4.w * wb2[3];
            }
        }
    }

    float cv[NT], hv[NT];
    #pragma unroll
    for (int n = 0; n < NT; n++) {
        float fc = __ldcg(&g_fcsum[s_node[n] * M + t]);
        float ig = sigf(a0[n]);
        float og = sigf(a1[n]);
        float ug = tanhf(a2[n]);
        cv[n] = ig * ug + fc;
        hv[n] = og * tanhf(cv[n]);
    }
    __syncthreads();                 // s_f reuse boundary
    #pragma unroll
    for (int n = 0; n < NT; n++) s_f[n * M + t] = hv[n];
    __syncthreads();

    float b[NT];
    #pragma unroll
    for (int n = 0; n < NT; n++)
        b[n] = bfh_t + g_fxp[s_ptok[n] * M + t];

    // ---- Wfh matvec: explicit two-phase weight double-buffer ----
    {
        float wa[4], wb[4];
        #pragma unroll
        for (int kk = 0; kk < 4; kk++)
            wa[kk] = Wfh[kk * M + t];
        #pragma unroll 1
        for (int k = 0; k < M; k += 8) {
            #pragma unroll
            for (int kk = 0; kk < 4; kk++)
                wb[kk] = Wfh[(k + 4 + kk) * M + t];
            #pragma unroll
            for (int n = 0; n < NT; n++) {
                const float4 h4 = *reinterpret_cast<const float4*>(s_f + n * M + k);
                b[n] += h4.x * wa[0] + h4.y * wa[1] + h4.z * wa[2] + h4.w * wa[3];
            }
            if (k + 8 < M) {
                #pragma unroll
                for (int kk = 0; kk < 4; kk++)
                    wa[kk] = Wfh[(k + 8 + kk) * M + t];
            }
            #pragma unroll
            for (int n = 0; n < NT; n++) {
                const float4 h4 = *reinterpret_cast<const float4*>(s_f + n * M + k + 4);
                b[n] += h4.x * wb[0] + h4.y * wb[1] + h4.z * wb[2] + h4.w * wb[3];
            }
        }
    }

    #pragma unroll
    for (int n = 0; n < NT; n++) {
        if (n < nn) {
            int node = s_node[n];
            if (node & (NNODE - 1)) {        // not a root
                float f = sigf(b[n]);
                atomicAdd(&g_hsum[s_parg[n] * M + t], hv[n]);
                atomicAdd(&g_fcsum[s_parg[n] * M + t], f * cv[n]);
            } else {
                g_croot[(node >> 16) * M + t] = cv[n];
            }
        }
    }
    // make this group's contributions globally visible, then push parents
    __threadfence();
    __syncthreads();
    if (t < nn) {
        int node = s_node[t];
        if (node & (NNODE - 1)) {
            int pg = s_parg[t];
            if (atomicSub(&g_pend[pg], 1) == 1) {
                int slot = atomicAdd(&g_qalloc, 1);
                atomicExch(&g_ready[slot], pg);
            }
        }
    }
    __syncthreads();
}

extern "C" __global__ void __launch_bounds__(256, 2)
treelstm_kernel(const int* __restrict__ l_tok, const int* __restrict__ l_par,
                const int* __restrict__ r_tok, const int* __restrict__ r_par,
                const float* __restrict__ emb,
                const float* __restrict__ Wioux, const float* __restrict__ bioux,
                const float* __restrict__ Wiouh, const float* __restrict__ biouh,
                const float* __restrict__ Wfx,   const float* __restrict__ bfx,
                const float* __restrict__ Wfh,   const float* __restrict__ bfh,
                const float* __restrict__ Wh,    const float* __restrict__ bh,
                const float* __restrict__ Wp,    const float* __restrict__ bp,
                float* __restrict__ out)
{
    __shared__ __align__(16) float s_f[16 * M];   // 16 KB, multi-purpose
    __shared__ int s_node[16], s_tok[16], s_parg[16], s_ptok[16];
    __shared__ int sh_pos, sh_nn, sh_more, sh_batch[16];

    const int t   = threadIdx.x;
    const int gid = blockIdx.x * blockDim.x + threadIdx.x;
    const int gs  = gridDim.x * blockDim.x;

    // ---------------- Phase 0: zero state + vocab projections ------------
    {
        float4 z4 = make_float4(0.f, 0.f, 0.f, 0.f);
        float4* h4p = reinterpret_cast<float4*>(g_hsum);
        float4* f4p = reinterpret_cast<float4*>(g_fcsum);
        const int n4 = TOT * M / 4;
        for (int i = gid; i < n4; i += gs) h4p[i] = z4;
        for (int i = gid; i < n4; i += gs) f4p[i] = z4;
        for (int i = gid; i < TOT; i += gs) {
            g_nchild[i] = 0; g_pend[i] = 0; g_ready[i] = -1;
        }
        if (gid == 0) { g_nleaf = 0; g_qalloc = 0; g_qhead = 0; }

        // vocab projections: groups of VNB vocab rows per block
        const int VG = VOCAB / VNB;   // 125
        for (int g = blockIdx.x; g < VG; g += gridDim.x) {
            #pragma unroll
            for (int n = 0; n < VNB; n++)
                s_f[n * M + t] = emb[(g * VNB + n) * M + t];
            __syncthreads();
            float a0[VNB], a1[VNB], a2[VNB], af[VNB];
            #pragma unroll
            for (int n = 0; n < VNB; n++) {
                a0[n] = bioux[t]; a1[n] = bioux[M + t];
                a2[n] = bioux[2 * M + t]; af[n] = bfx[t];
            }
            #pragma unroll 1
            for (int k = 0; k < M; k += 4) {
                #pragma unroll
                for (int kk = 0; kk < 4; kk++) {
                    float w0 = Wioux[(k + kk) * M3 + t];
                    float w1 = Wioux[(k + kk) * M3 + M + t];
                    float w2 = Wioux[(k + kk) * M3 + 2 * M + t];
                    float wf = Wfx[(k + kk) * M + t];
                    #pragma unroll
                    for (int n = 0; n < VNB; n++) {
                        float xv = s_f[n * M + k + kk];
                        a0[n] += xv * w0; a1[n] += xv * w1;
                        a2[n] += xv * w2; af[n] += xv * wf;
                    }
                }
            }
            #pragma unroll
            for (int n = 0; n < VNB; n++) {
                int v = g * VNB + n;
                g_ioux[v * M3 + t]         = a0[n];
                g_ioux[v * M3 + M + t]     = a1[n];
                g_ioux[v * M3 + 2 * M + t] = a2[n];
                g_fxp[v * M + t]           = af[n];
            }
            __syncthreads();
        }
    }
    gsync();

    // loop-invariant biases
    const float bio0 = biouh[t], bio1 = biouh[M + t], bio2 = biouh[2 * M + t];
    const float bfh_t = bfh[t];

    // ---------------- Phase 1: child counts (no depth walk needed) --------
    for (int i = gid; i < TOT; i += gs) {
        int tree = i >> 16, loc = i & (NNODE - 1);
        if (loc) {
            const int* parp = tree ? r_par : l_par;
            int pg = (tree << 16) + __ldg(parp + loc);
            atomicAdd(&g_nchild[pg], 1);
        }
    }
    gsync();

    // -------- Phase 1b: internal-children (pending) counts + leaf tables --
    for (int i = gid; i < TOT; i += gs) {
        int loc = i & (NNODE - 1);
        if (loc && __ldcg(&g_nchild[i]) > 0) {
            int tree = i >> 16;
            const int* parp = tree ? r_par : l_par;
            int pg = (tree << 16) + __ldg(parp + loc);
            atomicAdd(&g_pend[pg], 1);
        }
    }
    for (int i = gid; i < VOCAB * M; i += gs) {
        int v = i / M, e = i % M;
        float i0 = g_ioux[v * M3 + e]         + biouh[e];
        float i1 = g_ioux[v * M3 + M + e]     + biouh[M + e];
        float i2 = g_ioux[v * M3 + 2 * M + e] + biouh[2 * M + e];
        float c  = sigf(i0) * tanhf(i2);
        g_cleaf[i] = c;
        g_hleaf[i] = sigf(i1) * tanhf(c);
    }
    gsync();

    // ---- Phase 2: classify nodes (leaf list + initial ready); hfW table --
    for (int i = gid; i < TOT; i += gs) {
        if (__ldcg(&g_nchild[i]) > 0) {
            if (__ldcg(&g_pend[i]) == 0)          // all children are leaves
                g_ready[atomicAdd(&g_qalloc, 1)] = i;
        } else {
            g_leaf[atomicAdd(&g_nleaf, 1)] = i;
        }
    }
    {
        const int VG = VOCAB / VNB;   // 125
        for (int g = blockIdx.x; g < VG; g += gridDim.x) {
            #pragma unroll
            for (int n = 0; n < VNB; n++)
                s_f[n * M + t] = g_hleaf[(g * VNB + n) * M + t];
            __syncthreads();
            float bf[VNB];
            #pragma unroll
            for (int n = 0; n < VNB; n++) bf[n] = bfh_t;
            #pragma unroll 1
            for (int k = 0; k < M; k += 4) {
                #pragma unroll
                for (int kk = 0; kk < 4; kk++) {
                    float w = Wfh[(k + kk) * M + t];
                    #pragma unroll
                    for (int n = 0; n < VNB; n++)
                        bf[n] += s_f[n * M + k + kk] * w;
                }
            }
            #pragma unroll
            for (int n = 0; n < VNB; n++)
                g_hfw[(g * VNB + n) * M + t] = bf[n];
            __syncthreads();
        }
    }
    gsync();

    // ---------------- Phase 3: bulk leaf scatter ---------------------------
    {
        const int nleaf = __ldcg(&g_nleaf);
        const int ngrp = (nleaf + 7) / 8;
        for (int g = blockIdx.x; g < ngrp; g += gridDim.x) {
            const int base = g * 8;
            const int nn = min(8, nleaf - base);
            if (t < 8) {
                int node = g_leaf[base + ((t < nn) ? t : 0)];
                int tree = node >> 16, loc = node & (NNODE - 1);
                const int* tokp = tree ? r_tok : l_tok;
                const int* parp = tree ? r_par : l_par;
                int pl = parp[loc];
                s_node[t] = node;
                s_tok[t]  = tokp[loc];
                s_parg[t] = (tree << 16) + pl;
                s_ptok[t] = tokp[pl];
            }
            __syncthreads();
            #pragma unroll
            for (int n = 0; n < 8; n++) {
                if (n < nn) {
                    int v  = s_tok[n];
                    int pg = s_parg[n];
                    int pv = s_ptok[n];
                    float hl = g_hleaf[v * M + t];
                    float cl = g_cleaf[v * M + t];
                    float f  = sigf(g_hfw[v * M + t] + g_fxp[pv * M + t]);
                    atomicAdd(&g_hsum[pg * M + t], hl);
                    atomicAdd(&g_fcsum[pg * M + t], f * cl);
                }
            }
            __syncthreads();
        }
    }
    gsync();

    // ---------------- Phase 4: dataflow queue loop (no grid barriers) -----
    {
        const int n_int = TOT - __ldcg(&g_nleaf);
        for (;;) {
            if (t == 0) sh_pos = atomicAdd(&g_qhead, 16);
            __syncthreads();
            const int pos = sh_pos;
            __syncthreads();
            if (pos >= n_int) break;
            const int lim = min(16, n_int - pos);

            unsigned consumed = 0;              // meaningful on t==0 only
            int more = 1;
            while (more) {
                if (t == 0) {
                    const unsigned full = (1u << lim) - 1u;
                    int nn = 0;
                    while (nn == 0) {
                        for (int j = 0; j < lim; j++) {
                            if (!(consumed & (1u << j))) {
                                int v = *((volatile int*)&g_ready[pos + j]);
                                if (v >= 0) { sh_batch[nn++] = v; consumed |= (1u << j); }
                            }
                        }
                        if (nn == 0) __nanosleep(200);
                    }
                    sh_nn = nn;
                    sh_more = (consumed != full) ? 1 : 0;
                }
                __syncthreads();
                const int nn = sh_nn;
                more = sh_more;
                __threadfence();                // acquire: entries -> data reads
                if (nn > 8)
                    do_group<16>(sh_batch, nn, l_tok, l_par, r_tok, r_par, Wiouh, Wfh,
                                 bio0, bio1, bio2, bfh_t, s_f, s_node, s_tok, s_parg, s_ptok);
                else if (nn > 4)
                    do_group<8>(sh_batch, nn, l_tok, l_par, r_tok, r_par, Wiouh, Wfh,
                                bio0, bio1, bio2, bfh_t, s_f, s_node, s_tok, s_parg, s_ptok);
                else if (nn > 1)
                    do_group<4>(sh_batch, nn, l_tok, l_par, r_tok, r_par, Wiouh, Wfh,
                                bio0, bio1, bio2, bfh_t, s_f, s_node, s_tok, s_parg, s_ptok);
                else
                    do_group<1>(sh_batch, nn, l_tok, l_par, r_tok, r_par, Wiouh, Wfh,
                                bio0, bio1, bio2, bfh_t, s_f, s_node, s_tok, s_parg, s_ptok);
            }
        }
    }
    gsync();

    // ---------------- Phase 5: similarity head (block 0) ------------------
    if (blockIdx.x == 0) {
        float cl = __ldcg(&g_croot[t]);
        float cr = __ldcg(&g_croot[M + t]);
        s_f[t]     = cl * cr;
        s_f[M + t] = fabsf(cl - cr);
        __syncthreads();
        float acc = bh[t];
        for (int k = 0; k < 2 * M; k++) acc += s_f[k] * Wh[k * M + t];
        float hid = sigf(acc);
        s_f[2 * M + t] = hid * Wp[2 * t];
        s_f[3 * M + t] = hid * Wp[2 * t + 1];
        __syncthreads();
        if (t == 0) {
            float l0 = bp[0], l1 = bp[1];
            for (int k = 0; k < M; k++) { l0 += s_f[2 * M + k]; l1 += s_f[3 * M + k]; }
            float mx = fmaxf(l0, l1);
            float e0 = expf(l0 - mx), e1 = expf(l1 - mx);
            float inv = 1.0f / (e0 + e1);
            out[0] = e0 * inv;
            out[1] = e1 * inv;
        }
    }
}

extern "C" void kernel_launch(void* const* d_in, const int* in_sizes, int n_in,
                              void* d_out, int out_size)
{
    (void)in_sizes; (void)n_in; (void)out_size;
    int dev = 0;
    cudaGetDevice(&dev);
    int nsm = 0;
    cudaDeviceGetAttribute(&nsm, cudaDevAttrMultiProcessorCount, dev);
    if (nsm <= 0) nsm = 148;

    treelstm_kernel<<<2 * nsm, 256>>>(
        (const int*)d_in[0], (const int*)d_in[1],
        (const int*)d_in[2], (const int*)d_in[3],
        (const float*)d_in[4],
        (const float*)d_in[5], (const float*)d_in[6],
        (const float*)d_in[7], (const float*)d_in[8],
        (const float*)d_in[9], (const float*)d_in[10],
        (const float*)d_in[11], (const float*)d_in[12],
        (const float*)d_in[13], (const float*)d_in[14],
        (const float*)d_in[15], (const float*)d_in[16],
        (float*)d_out);
}

// round 12
// speedup vs baseline: 1.1692x; 1.1692x over previous
#include <cuda_runtime.h>
#include <math.h>

// SimilarityTreeLSTM on GB300: persistent kernel, height-frontier rounds.
//
// R12 = R7 core (leaf elimination, NT-adaptive 16-node groups, barrier per
// round) with:
//  * height-frontier scheduling: append-only ready list g_order + g_alloc;
//    the grid barrier's last arriver snapshots g_alloc -> g_re, so each
//    round processes [rs, re) with no extra barriers. Front-loaded round
//    sizes reduce wave quantization vs depth levels; depth walk/hist/scan
//    phases deleted (setup 6 gsyncs -> 4).
//  * zero only INTERNAL rows of hsum/fcsum (268 -> ~134 MB)
//  * traffic-aware NT choice over {16,8,4,2,1}:
//    cost = batches * max(NT*455 [fma], gw*10 [weight stream], 250 [lat])

#define NNODE 65536
#define TOT   (2 * NNODE)
#define M     256
#define M3    (3 * M)
#define VOCAB 1000
#define VNB   8

// ---------------- device scratch (static: no allocations allowed) ----------
__device__ float g_hsum[TOT * M];        // children h sum (internal rows only)
__device__ float g_fcsum[TOT * M];       // children f*c sum
__device__ float g_ioux[VOCAB * M3];     // vocab proj: emb@Wioux + bioux
__device__ float g_fxp[VOCAB * M];       // vocab proj: emb@Wfx + bfx
__device__ float g_hleaf[VOCAB * M];     // leaf h by token
__device__ float g_cleaf[VOCAB * M];     // leaf c by token
__device__ float g_hfw[VOCAB * M];       // h_leaf @ Wfh + bfh
__device__ int   g_nchild[TOT];
__device__ int   g_pend[TOT];            // remaining internal children
__device__ int   g_order[TOT];           // append-only ready list
__device__ int   g_alloc;                // next free slot in g_order
__device__ int   g_re;                   // round-end snapshot (set in barrier)
__device__ float g_croot[2 * M];
__device__ unsigned g_barcnt;
__device__ unsigned g_sense;

__device__ __forceinline__ float sigf(float x) {
    return 1.0f / (1.0f + expf(-x));
}

// Sense-reversal grid barrier; last arriver snapshots g_alloc into g_re
// before releasing, so all blocks see a consistent round boundary.
__device__ __forceinline__ void gsync() {
    __syncthreads();
    if (threadIdx.x == 0) {
        __threadfence();
        unsigned target = *((volatile unsigned*)&g_sense) + 1u;
        unsigned a = atomicAdd(&g_barcnt, 1u);
        if (a == gridDim.x - 1u) {
            g_barcnt = 0u;
            g_re = *((volatile int*)&g_alloc);
            __threadfence();
            atomicExch(&g_sense, target);
        } else {
            while (*((volatile unsigned*)&g_sense) != target) { __nanosleep(64); }
        }
        __threadfence();
    }
    __syncthreads();
}

// Process one round's sub-range [rs, rs+cnt) of g_order, NT nodes per group.
template <int NT>
__device__ void do_round(int rs, int cnt,
                         const int* __restrict__ l_tok, const int* __restrict__ l_par,
                         const int* __restrict__ r_tok, const int* __restrict__ r_par,
                         const float* __restrict__ Wiouh, const float* __restrict__ Wfh,
                         float bio0, float bio1, float bio2, float bfh_t,
                         float* s_f, int* s_node, int* s_tok, int* s_parg, int* s_ptok)
{
    const int t = threadIdx.x;
    const int ngrp = (cnt + NT - 1) / NT;

    for (int g = blockIdx.x; g < ngrp; g += gridDim.x) {
        const int base = rs + g * NT;
        const int nn   = min(NT, cnt - g * NT);
        if (t < NT) {
            int idx  = base + ((t < nn) ? t : 0);    // clamp (dup node 0 of grp)
            int node = g_order[idx];
            int tree = node >> 16, loc = node & (NNODE - 1);
            const int* tokp = tree ? r_tok : l_tok;
            const int* parp = tree ? r_par : l_par;
            int pl = parp[loc];
            s_node[t] = node;
            s_tok[t]  = tokp[loc];
            s_parg[t] = (tree << 16) + pl;
            s_ptok[t] = tokp[pl];
        }
        __syncthreads();
        // load children h sums (bypass L1: updated via L2 atomics)
        #pragma unroll
        for (int n = 0; n < NT; n++)
            s_f[n * M + t] = __ldcg(&g_hsum[s_node[n] * M + t]);
        __syncthreads();

        float a0[NT], a1[NT], a2[NT];
        #pragma unroll
        for (int n = 0; n < NT; n++) {
            int tk = s_tok[n];
            a0[n] = g_ioux[tk * M3 + t]         + bio0;
            a1[n] = g_ioux[tk * M3 + M + t]     + bio1;
            a2[n] = g_ioux[tk * M3 + 2 * M + t] + bio2;
        }

        // ---- Wiouh matvec: explicit two-phase weight double-buffer ----
        {
            float wa0[4], wa1[4], wa2[4], wb0[4], wb1[4], wb2[4];
            #pragma unroll
            for (int kk = 0; kk < 4; kk++) {
                wa0[kk] = Wiouh[kk * M3 + t];
                wa1[kk] = Wiouh[kk * M3 + M + t];
                wa2[kk] = Wiouh[kk * M3 + 2 * M + t];
            }
            #pragma unroll 1
            for (int k = 0; k < M; k += 8) {
                #pragma unroll
                for (int kk = 0; kk < 4; kk++) {
                    wb0[kk] = Wiouh[(k + 4 + kk) * M3 + t];
                    wb1[kk] = Wiouh[(k + 4 + kk) * M3 + M + t];
                    wb2[kk] = Wiouh[(k + 4 + kk) * M3 + 2 * M + t];
                }
                #pragma unroll
                for (int n = 0; n < NT; n++) {
                    const float4 h4 = *reinterpret_cast<const float4*>(s_f + n * M + k);
                    a0[n] += h4.x * wa0[0]; a1[n] += h4.x * wa1[0]; a2[n] += h4.x * wa2[0];
                    a0[n] += h4.y * wa0[1]; a1[n] += h4.y * wa1[1]; a2[n] += h4.y * wa2[1];
                    a0[n] += h4.z * wa0[2]; a1[n] += h4.z * wa1[2]; a2[n] += h4.z * wa2[2];
                    a0[n] += h4.w * wa0[3]; a1[n] += h4.w * wa1[3]; a2[n] += h4.w * wa2[3];
                }
                if (k + 8 < M) {
                    #pragma unroll
                    for (int kk = 0; kk < 4; kk++) {
                        wa0[kk] = Wiouh[(k + 8 + kk) * M3 + t];
                        wa1[kk] = Wiouh[(k + 8 + kk) * M3 + M + t];
                        wa2[kk] = Wiouh[(k + 8 + kk) * M3 + 2 * M + t];
                    }
                }
                #pragma unroll
                for (int n = 0; n < NT; n++) {
                    const float4 h4 = *reinterpret_cast<const float4*>(s_f + n * M + k + 4);
                    a0[n] += h4.x * wb0[0]; a1[n] += h4.x * wb1[0]; a2[n] += h4.x * wb2[0];
                    a0[n] += h4.y * wb0[1]; a1[n] += h4.y * wb1[1]; a2[n] += h4.y * wb2[1];
                    a0[n] += h4.z * wb0[2]; a1[n] += h4.z * wb1[2]; a2[n] += h4.z * wb2[2];
                    a0[n] += h4.w * wb0[3]; a1[n] += h4.w * wb1[3]; a2[n] += h4.w * wb2[3];
                }
            }
        }

        float cv[NT], hv[NT];
        #pragma unroll
        for (int n = 0; n < NT; n++) {
            float fc = __ldcg(&g_fcsum[s_node[n] * M + t]);
            float ig = sigf(a0[n]);
            float og = sigf(a1[n]);
            float ug = tanhf(a2[n]);
            cv[n] = ig * ug + fc;
            hv[n] = og * tanhf(cv[n]);
        }
        __syncthreads();                 // s_f reuse boundary
        #pragma unroll
        for (int n = 0; n < NT; n++) s_f[n * M + t] = hv[n];
        __syncthreads();

        float b[NT];
        #pragma unroll
        for (int n = 0; n < NT; n++)
            b[n] = bfh_t + g_fxp[s_ptok[n] * M + t];

        // ---- Wfh matvec: explicit two-phase weight double-buffer ----
        {
            float wa[4], wb[4];
            #pragma unroll
            for (int kk = 0; kk < 4; kk++)
                wa[kk] = Wfh[kk * M + t];
            #pragma unroll 1
            for (int k = 0; k < M; k += 8) {
                #pragma unroll
                for (int kk = 0; kk < 4; kk++)
                    wb[kk] = Wfh[(k + 4 + kk) * M + t];
                #pragma unroll
                for (int n = 0; n < NT; n++) {
                    const float4 h4 = *reinterpret_cast<const float4*>(s_f + n * M + k);
                    b[n] += h4.x * wa[0] + h4.y * wa[1] + h4.z * wa[2] + h4.w * wa[3];
                }
                if (k + 8 < M) {
                    #pragma unroll
                    for (int kk = 0; kk < 4; kk++)
                        wa[kk] = Wfh[(k + 8 + kk) * M + t];
                }
                #pragma unroll
                for (int n = 0; n < NT; n++) {
                    const float4 h4 = *reinterpret_cast<const float4*>(s_f + n * M + k + 4);
                    b[n] += h4.x * wb[0] + h4.y * wb[1] + h4.z * wb[2] + h4.w * wb[3];
                }
            }
        }

        #pragma unroll
        for (int n = 0; n < NT; n++) {
            if (n < nn) {
                int node = s_node[n];
                if (node & (NNODE - 1)) {        // not a root
                    float f = sigf(b[n]);
                    atomicAdd(&g_hsum[s_parg[n] * M + t], hv[n]);
                    atomicAdd(&g_fcsum[s_parg[n] * M + t], f * cv[n]);
                } else {
                    g_croot[(node >> 16) * M + t] = cv[n];
                }
            }
        }
        __syncthreads();
        // last-finishing child pushes parent (consumed only after next gsync,
        // whose fences make both the data atomics and this store visible)
        if (t < nn) {
            int node = s_node[t];
            if (node & (NNODE - 1)) {
                int pg = s_parg[t];
                if (atomicSub(&g_pend[pg], 1) == 1) {
                    int pos = atomicAdd(&g_alloc, 1);
                    g_order[pos] = pg;
                }
            }
        }
        __syncthreads();
    }
}

extern "C" __global__ void __launch_bounds__(256, 2)
treelstm_kernel(const int* __restrict__ l_tok, const int* __restrict__ l_par,
                const int* __restrict__ r_tok, const int* __restrict__ r_par,
                const float* __restrict__ emb,
                const float* __restrict__ Wioux, const float* __restrict__ bioux,
                const float* __restrict__ Wiouh, const float* __restrict__ biouh,
                const float* __restrict__ Wfx,   const float* __restrict__ bfx,
                const float* __restrict__ Wfh,   const float* __restrict__ bfh,
                const float* __restrict__ Wh,    const float* __restrict__ bh,
                const float* __restrict__ Wp,    const float* __restrict__ bp,
                float* __restrict__ out)
{
    __shared__ __align__(16) float s_f[16 * M];   // 16 KB, multi-purpose
    __shared__ int s_node[16], s_tok[16], s_parg[16], s_ptok[16];
    __shared__ int s_isleaf[16];

    const int t   = threadIdx.x;
    const int gid = blockIdx.x * blockDim.x + threadIdx.x;
    const int gs  = gridDim.x * blockDim.x;

    // ------- Phase 0: zero counters + vocab projections -------------------
    {
        for (int i = gid; i < TOT; i += gs) { g_nchild[i] = 0; g_pend[i] = 0; }
        if (gid == 0) g_alloc = 0;

        const int VG = VOCAB / VNB;   // 125
        for (int g = blockIdx.x; g < VG; g += gridDim.x) {
            #pragma unroll
            for (int n = 0; n < VNB; n++)
                s_f[n * M + t] = emb[(g * VNB + n) * M + t];
            __syncthreads();
            float a0[VNB], a1[VNB], a2[VNB], af[VNB];
            #pragma unroll
            for (int n = 0; n < VNB; n++) {
                a0[n] = bioux[t]; a1[n] = bioux[M + t];
                a2[n] = bioux[2 * M + t]; af[n] = bfx[t];
            }
            #pragma unroll 1
            for (int k = 0; k < M; k += 4) {
                #pragma unroll
                for (int kk = 0; kk < 4; kk++) {
                    float w0 = Wioux[(k + kk) * M3 + t];
                    float w1 = Wioux[(k + kk) * M3 + M + t];
                    float w2 = Wioux[(k + kk) * M3 + 2 * M + t];
                    float wf = Wfx[(k + kk) * M + t];
                    #pragma unroll
                    for (int n = 0; n < VNB; n++) {
                        float xv = s_f[n * M + k + kk];
                        a0[n] += xv * w0; a1[n] += xv * w1;
                        a2[n] += xv * w2; af[n] += xv * wf;
                    }
                }
            }
            #pragma unroll
            for (int n = 0; n < VNB; n++) {
                int v = g * VNB + n;
                g_ioux[v * M3 + t]         = a0[n];
                g_ioux[v * M3 + M + t]     = a1[n];
                g_ioux[v * M3 + 2 * M + t] = a2[n];
                g_fxp[v * M + t]           = af[n];
            }
            __syncthreads();
        }
    }
    gsync();

    // loop-invariant biases
    const float bio0 = biouh[t], bio1 = biouh[M + t], bio2 = biouh[2 * M + t];
    const float bfh_t = bfh[t];

    // ------- Phase 1: child counts + leaf h/c tables ----------------------
    for (int i = gid; i < TOT; i += gs) {
        int tree = i >> 16, loc = i & (NNODE - 1);
        if (loc) {
            const int* parp = tree ? r_par : l_par;
            atomicAdd(&g_nchild[(tree << 16) + __ldg(parp + loc)], 1);
        }
    }
    for (int i = gid; i < VOCAB * M; i += gs) {
        int v = i / M, e = i % M;
        float i0 = g_ioux[v * M3 + e]         + biouh[e];
        float i1 = g_ioux[v * M3 + M + e]     + biouh[M + e];
        float i2 = g_ioux[v * M3 + 2 * M + e] + biouh[2 * M + e];
        float c  = sigf(i0) * tanhf(i2);
        g_cleaf[i] = c;
        g_hleaf[i] = sigf(i1) * tanhf(c);
    }
    gsync();

    // ------- Phase 2: pend counts + zero internal rows + hfW table --------
    for (int i = gid; i < TOT; i += gs) {
        int loc = i & (NNODE - 1);
        if (loc && __ldcg(&g_nchild[i]) > 0) {
            int tree = i >> 16;
            const int* parp = tree ? r_par : l_par;
            atomicAdd(&g_pend[(tree << 16) + __ldg(parp + loc)], 1);
        }
    }
    {
        // zero only internal rows (leaf rows never read)
        const int wid_g = gid >> 5, lane = gid & 31, nw = gs >> 5;
        const float4 z4 = make_float4(0.f, 0.f, 0.f, 0.f);
        for (int i = wid_g; i < TOT; i += nw) {
            if (__ldcg(&g_nchild[i]) > 0) {
                float4* hp = reinterpret_cast<float4*>(&g_hsum[(long)i * M]);
                float4* fp = reinterpret_cast<float4*>(&g_fcsum[(long)i * M]);
                hp[lane] = z4; hp[lane + 32] = z4;
                fp[lane] = z4; fp[lane + 32] = z4;
            }
        }
    }
    {
        const int VG = VOCAB / VNB;   // 125
        for (int g = blockIdx.x; g < VG; g += gridDim.x) {
            #pragma unroll
            for (int n = 0; n < VNB; n++)
                s_f[n * M + t] = g_hleaf[(g * VNB + n) * M + t];
            __syncthreads();
            float bf[VNB];
            #pragma unroll
            for (int n = 0; n < VNB; n++) bf[n] = bfh_t;
            #pragma unroll 1
            for (int k = 0; k < M; k += 4) {
                #pragma unroll
                for (int kk = 0; kk < 4; kk++) {
                    float w = Wfh[(k + kk) * M + t];
                    #pragma unroll
                    for (int n = 0; n < VNB; n++)
                        bf[n] += s_f[n * M + k + kk] * w;
                }
            }
            #pragma unroll
            for (int n = 0; n < VNB; n++)
                g_hfw[(g * VNB + n) * M + t] = bf[n];
            __syncthreads();
        }
    }
    gsync();

    // ------- Phase 3: classify+push round 0; leaf scatter by chunk --------
    for (int i = gid; i < TOT; i += gs) {
        if (__ldcg(&g_nchild[i]) > 0 && __ldcg(&g_pend[i]) == 0)
            g_order[atomicAdd(&g_alloc, 1)] = i;
    }
    {
        const int ngrp = TOT / 8;
        for (int g = blockIdx.x; g < ngrp; g += gridDim.x) {
            const int base = g * 8;
            if (t < 8) {
                int node = base + t;               // consecutive ids: coalesced
                int tree = node >> 16, loc = node & (NNODE - 1);
                const int* tokp = tree ? r_tok : l_tok;
                const int* parp = tree ? r_par : l_par;
                int isleaf = (loc != 0) && (__ldcg(&g_nchild[node]) == 0);
                s_isleaf[t] = isleaf;
                if (isleaf) {
                    int pl = parp[loc];
                    s_tok[t]  = tokp[loc];
                    s_parg[t] = (tree << 16) + pl;
                    s_ptok[t] = tokp[pl];
                }
            }
            __syncthreads();
            #pragma unroll
            for (int n = 0; n < 8; n++) {
                if (s_isleaf[n]) {
                    int v  = s_tok[n];
                    int pg = s_parg[n];
                    int pv = s_ptok[n];
                    float hl = g_hleaf[v * M + t];
                    float cl = g_cleaf[v * M + t];
                    float f  = sigf(g_hfw[v * M + t] + g_fxp[pv * M + t]);
                    atomicAdd(&g_hsum[pg * M + t], hl);
                    atomicAdd(&g_fcsum[pg * M + t], f * cl);
                }
            }
            __syncthreads();
        }
    }
    gsync();   // snapshots g_alloc -> g_re (round 0 boundary)

    // ------- Phase 4: height-frontier round loop ---------------------------
    {
        const int G = gridDim.x;
        int rs = 0;
        int re = __ldcg(&g_re);
        while (rs < re) {
            const int cnt = re - rs;
            // traffic-aware NT pick: cost = batches * max(fma, weights, floor)
            long best = 0x7fffffffffffL; int bestNT = 16;
            #pragma unroll
            for (int ntI = 0; ntI < 5; ntI++) {
                const int NTc = (ntI == 0) ? 16 : (ntI == 1) ? 8 : (ntI == 2) ? 4
                              : (ntI == 3) ? 2 : 1;
                int grp = (cnt + NTc - 1) / NTc;
                int bat = (grp + G - 1) / G;
                int gw  = grp < G ? grp : G;
                int wc  = NTc * 455;
                if (gw * 10 > wc) wc = gw * 10;
                if (wc < 250) wc = 250;
                long c = (long)bat * wc;
                if (c < best) { best = c; bestNT = NTc; }
            }
            if (bestNT == 16)
                do_round<16>(rs, cnt, l_tok, l_par, r_tok, r_par, Wiouh, Wfh,
                             bio0, bio1, bio2, bfh_t, s_f, s_node, s_tok, s_parg, s_ptok);
            else if (bestNT == 8)
                do_round<8>(rs, cnt, l_tok, l_par, r_tok, r_par, Wiouh, Wfh,
                            bio0, bio1, bio2, bfh_t, s_f, s_node, s_tok, s_parg, s_ptok);
            else if (bestNT == 4)
                do_round<4>(rs, cnt, l_tok, l_par, r_tok, r_par, Wiouh, Wfh,
                            bio0, bio1, bio2, bfh_t, s_f, s_node, s_tok, s_parg, s_ptok);
            else if (bestNT == 2)
                do_round<2>(rs, cnt, l_tok, l_par, r_tok, r_par, Wiouh, Wfh,
                            bio0, bio1, bio2, bfh_t, s_f, s_node, s_tok, s_parg, s_ptok);
            else
                do_round<1>(rs, cnt, l_tok, l_par, r_tok, r_par, Wiouh, Wfh,
                            bio0, bio1, bio2, bfh_t, s_f, s_node, s_tok, s_parg, s_ptok);
            gsync();                      // drains data + snapshots next re
            rs = re;
            re = __ldcg(&g_re);
        }
    }

    // ------- Phase 5: similarity head (block 0) ----------------------------
    if (blockIdx.x == 0) {
        float cl = __ldcg(&g_croot[t]);
        float cr = __ldcg(&g_croot[M + t]);
        s_f[t]     = cl * cr;
        s_f[M + t] = fabsf(cl - cr);
        __syncthreads();
        float acc = bh[t];
        for (int k = 0; k < 2 * M; k++) acc += s_f[k] * Wh[k * M + t];
        float hid = sigf(acc);
        s_f[2 * M + t] = hid * Wp[2 * t];
        s_f[3 * M + t] = hid * Wp[2 * t + 1];
        __syncthreads();
        if (t == 0) {
            float l0 = bp[0], l1 = bp[1];
            for (int k = 0; k < M; k++) { l0 += s_f[2 * M + k]; l1 += s_f[3 * M + k]; }
            float mx = fmaxf(l0, l1);
            float e0 = expf(l0 - mx), e1 = expf(l1 - mx);
            float inv = 1.0f / (e0 + e1);
            out[0] = e0 * inv;
            out[1] = e1 * inv;
        }
    }
}

extern "C" void kernel_launch(void* const* d_in, const int* in_sizes, int n_in,
                              void* d_out, int out_size)
{
    (void)in_sizes; (void)n_in; (void)out_size;
    int dev = 0;
    cudaGetDevice(&dev);
    int nsm = 0;
    cudaDeviceGetAttribute(&nsm, cudaDevAttrMultiProcessorCount, dev);
    if (nsm <= 0) nsm = 148;

    treelstm_kernel<<<2 * nsm, 256>>>(
        (const int*)d_in[0], (const int*)d_in[1],
        (const int*)d_in[2], (const int*)d_in[3],
        (const float*)d_in[4],
        (const float*)d_in[5], (const float*)d_in[6],
        (const float*)d_in[7], (const float*)d_in[8],
        (const float*)d_in[9], (const float*)d_in[10],
        (const float*)d_in[11], (const float*)d_in[12],
        (const float*)d_in[13], (const float*)d_in[14],
        (const float*)d_in[15], (const float*)d_in[16],
        (float*)d_out);
}

// round 13
// speedup vs baseline: 1.1951x; 1.0222x over previous
#include <cuda_runtime.h>
#include <math.h>

// SimilarityTreeLSTM on GB300: persistent kernel, height-frontier rounds.
//
// R13 = R12 (height-frontier rounds, adaptive NT) with scatter -> gather:
//  * children plain-store their own h and f*c once (g_h/g_fc); parents
//    gather via a CSR children list. NO atomics in the recurrence, NO
//    zero-init of state arrays, NO leaf-scatter phase (leaf children are
//    read straight from the L2-resident vocab tables during the gather).
//  * CSR built in setup: nchild count -> 3-step parallel prefix scan ->
//    fill (leaf children encoded as sign-bit|token).

#define NNODE 65536
#define TOT   (2 * NNODE)
#define M     256
#define M3    (3 * M)
#define VOCAB 1000
#define VNB   8

// ---------------- device scratch (static: no allocations allowed) ----------
__device__ float g_h[TOT * M];           // internal node h (written once)
__device__ float g_fc[TOT * M];          // internal node f*c (written once)
__device__ float g_ioux[VOCAB * M3];     // vocab proj: emb@Wioux + bioux
__device__ float g_fxp[VOCAB * M];       // vocab proj: emb@Wfx + bfx
__device__ float g_hleaf[VOCAB * M];     // leaf h by token
__device__ float g_cleaf[VOCAB * M];     // leaf c by token
__device__ float g_hfw[VOCAB * M];       // h_leaf @ Wfh + bfh
__device__ int   g_nchild[TOT];
__device__ int   g_pend[TOT];            // remaining internal children
__device__ int   g_cstart[TOT];          // CSR segment start
__device__ int   g_ccur[TOT];            // CSR fill cursor
__device__ int   g_child[TOT];           // CSR entries (<0: leaf, low bits=token)
__device__ int   g_bsum[1024];           // per-block partial sums for scan
__device__ int   g_order[TOT];           // append-only ready list
__device__ int   g_alloc;                // next free slot in g_order
__device__ int   g_re;                   // round-end snapshot (set in barrier)
__device__ float g_croot[2 * M];
__device__ unsigned g_barcnt;
__device__ unsigned g_sense;

__device__ __forceinline__ float sigf(float x) {
    return 1.0f / (1.0f + expf(-x));
}

// Sense-reversal grid barrier; last arriver snapshots g_alloc into g_re.
__device__ __forceinline__ void gsync() {
    __syncthreads();
    if (threadIdx.x == 0) {
        __threadfence();
        unsigned target = *((volatile unsigned*)&g_sense) + 1u;
        unsigned a = atomicAdd(&g_barcnt, 1u);
        if (a == gridDim.x - 1u) {
            g_barcnt = 0u;
            g_re = *((volatile int*)&g_alloc);
            __threadfence();
            atomicExch(&g_sense, target);
        } else {
            while (*((volatile unsigned*)&g_sense) != target) { __nanosleep(64); }
        }
        __threadfence();
    }
    __syncthreads();
}

// Process one round's sub-range [rs, rs+cnt) of g_order, NT nodes per group.
template <int NT>
__device__ void do_round(int rs, int cnt,
                         const int* __restrict__ l_tok, const int* __restrict__ l_par,
                         const int* __restrict__ r_tok, const int* __restrict__ r_par,
                         const float* __restrict__ Wiouh, const float* __restrict__ Wfh,
                         float bio0, float bio1, float bio2, float bfh_t,
                         float* s_f, float* s_fc,
                         int* s_node, int* s_tok, int* s_parg, int* s_ptok,
                         int* s_cs, int* s_ce)
{
    const int t = threadIdx.x;
    const int ngrp = (cnt + NT - 1) / NT;

    for (int g = blockIdx.x; g < ngrp; g += gridDim.x) {
        const int base = rs + g * NT;
        const int nn   = min(NT, cnt - g * NT);
        if (t < NT) {
            int idx  = base + ((t < nn) ? t : 0);    // clamp (dup node 0 of grp)
            int node = g_order[idx];
            int tree = node >> 16, loc = node & (NNODE - 1);
            const int* tokp = tree ? r_tok : l_tok;
            const int* parp = tree ? r_par : l_par;
            int pl = parp[loc];
            s_node[t] = node;
            s_tok[t]  = tokp[loc];
            s_parg[t] = (tree << 16) + pl;
            s_ptok[t] = tokp[pl];
            s_cs[t]   = g_cstart[node];
            s_ce[t]   = s_cs[t] + __ldcg(&g_nchild[node]);
        }
        __syncthreads();

        // gather children: leaves from vocab tables, internal from g_h/g_fc
        #pragma unroll
        for (int n = 0; n < NT; n++) {
            float hs = 0.f, fcs = 0.f;
            const float fxv = g_fxp[s_tok[n] * M + t];
            const int ce = s_ce[n];
            for (int j = s_cs[n]; j < ce; j++) {
                int e = __ldg(&g_child[j]);
                if (e < 0) {
                    int v = e & 0xFFFF;
                    hs  += g_hleaf[v * M + t];
                    fcs += sigf(g_hfw[v * M + t] + fxv) * g_cleaf[v * M + t];
                } else {
                    hs  += __ldcg(&g_h[(long)e * M + t]);
                    fcs += __ldcg(&g_fc[(long)e * M + t]);
                }
            }
            s_f[n * M + t]  = hs;
            s_fc[n * M + t] = fcs;
        }
        __syncthreads();

        float a0[NT], a1[NT], a2[NT];
        #pragma unroll
        for (int n = 0; n < NT; n++) {
            int tk = s_tok[n];
            a0[n] = g_ioux[tk * M3 + t]         + bio0;
            a1[n] = g_ioux[tk * M3 + M + t]     + bio1;
            a2[n] = g_ioux[tk * M3 + 2 * M + t] + bio2;
        }

        // ---- Wiouh matvec: explicit two-phase weight double-buffer ----
        {
            float wa0[4], wa1[4], wa2[4], wb0[4], wb1[4], wb2[4];
            #pragma unroll
            for (int kk = 0; kk < 4; kk++) {
                wa0[kk] = Wiouh[kk * M3 + t];
                wa1[kk] = Wiouh[kk * M3 + M + t];
                wa2[kk] = Wiouh[kk * M3 + 2 * M + t];
            }
            #pragma unroll 1
            for (int k = 0; k < M; k += 8) {
                #pragma unroll
                for (int kk = 0; kk < 4; kk++) {
                    wb0[kk] = Wiouh[(k + 4 + kk) * M3 + t];
                    wb1[kk] = Wiouh[(k + 4 + kk) * M3 + M + t];
                    wb2[kk] = Wiouh[(k + 4 + kk) * M3 + 2 * M + t];
                }
                #pragma unroll
                for (int n = 0; n < NT; n++) {
                    const float4 h4 = *reinterpret_cast<const float4*>(s_f + n * M + k);
                    a0[n] += h4.x * wa0[0]; a1[n] += h4.x * wa1[0]; a2[n] += h4.x * wa2[0];
                    a0[n] += h4.y * wa0[1]; a1[n] += h4.y * wa1[1]; a2[n] += h4.y * wa2[1];
                    a0[n] += h4.z * wa0[2]; a1[n] += h4.z * wa1[2]; a2[n] += h4.z * wa2[2];
                    a0[n] += h4.w * wa0[3]; a1[n] += h4.w * wa1[3]; a2[n] += h4.w * wa2[3];
                }
                if (k + 8 < M) {
                    #pragma unroll
                    for (int kk = 0; kk < 4; kk++) {
                        wa0[kk] = Wiouh[(k + 8 + kk) * M3 + t];
                        wa1[kk] = Wiouh[(k + 8 + kk) * M3 + M + t];
                        wa2[kk] = Wiouh[(k + 8 + kk) * M3 + 2 * M + t];
                    }
                }
                #pragma unroll
                for (int n = 0; n < NT; n++) {
                    const float4 h4 = *reinterpret_cast<const float4*>(s_f + n * M + k + 4);
                    a0[n] += h4.x * wb0[0]; a1[n] += h4.x * wb1[0]; a2[n] += h4.x * wb2[0];
                    a0[n] += h4.y * wb0[1]; a1[n] += h4.y * wb1[1]; a2[n] += h4.y * wb2[1];
                    a0[n] += h4.z * wb0[2]; a1[n] += h4.z * wb1[2]; a2[n] += h4.z * wb2[2];
                    a0[n] += h4.w * wb0[3]; a1[n] += h4.w * wb1[3]; a2[n] += h4.w * wb2[3];
                }
            }
        }

        float cv[NT], hv[NT];
        #pragma unroll
        for (int n = 0; n < NT; n++) {
            float fc = s_fc[n * M + t];
            float ig = sigf(a0[n]);
            float og = sigf(a1[n]);
            float ug = tanhf(a2[n]);
            cv[n] = ig * ug + fc;
            hv[n] = og * tanhf(cv[n]);
        }
        __syncthreads();                 // s_f reuse boundary
        #pragma unroll
        for (int n = 0; n < NT; n++) s_f[n * M + t] = hv[n];
        __syncthreads();

        float b[NT];
        #pragma unroll
        for (int n = 0; n < NT; n++)
            b[n] = bfh_t + g_fxp[s_ptok[n] * M + t];

        // ---- Wfh matvec: explicit two-phase weight double-buffer ----
        {
            float wa[4], wb[4];
            #pragma unroll
            for (int kk = 0; kk < 4; kk++)
                wa[kk] = Wfh[kk * M + t];
            #pragma unroll 1
            for (int k = 0; k < M; k += 8) {
                #pragma unroll
                for (int kk = 0; kk < 4; kk++)
                    wb[kk] = Wfh[(k + 4 + kk) * M + t];
                #pragma unroll
                for (int n = 0; n < NT; n++) {
                    const float4 h4 = *reinterpret_cast<const float4*>(s_f + n * M + k);
                    b[n] += h4.x * wa[0] + h4.y * wa[1] + h4.z * wa[2] + h4.w * wa[3];
                }
                if (k + 8 < M) {
                    #pragma unroll
                    for (int kk = 0; kk < 4; kk++)
                        wa[kk] = Wfh[(k + 8 + kk) * M + t];
                }
                #pragma unroll
                for (int n = 0; n < NT; n++) {
                    const float4 h4 = *reinterpret_cast<const float4*>(s_f + n * M + k + 4);
                    b[n] += h4.x * wb[0] + h4.y * wb[1] + h4.z * wb[2] + h4.w * wb[3];
                }
            }
        }

        // plain stores (no atomics): each internal node writes its own rows
        #pragma unroll
        for (int n = 0; n < NT; n++) {
            if (n < nn) {
                int node = s_node[n];
                if (node & (NNODE - 1)) {        // not a root
                    float f = sigf(b[n]);
                    g_h[(long)node * M + t]  = hv[n];
                    g_fc[(long)node * M + t] = f * cv[n];
                } else {
                    g_croot[(node >> 16) * M + t] = cv[n];
                }
            }
        }
        __syncthreads();
        // last-finishing child pushes parent (consumed only after next gsync)
        if (t < nn) {
            int node = s_node[t];
            if (node & (NNODE - 1)) {
                int pg = s_parg[t];
                if (atomicSub(&g_pend[pg], 1) == 1) {
                    int pos = atomicAdd(&g_alloc, 1);
                    g_order[pos] = pg;
                }
            }
        }
        __syncthreads();
    }
}

extern "C" __global__ void __launch_bounds__(256, 2)
treelstm_kernel(const int* __restrict__ l_tok, const int* __restrict__ l_par,
                const int* __restrict__ r_tok, const int* __restrict__ r_par,
                const float* __restrict__ emb,
                const float* __restrict__ Wioux, const float* __restrict__ bioux,
                const float* __restrict__ Wiouh, const float* __restrict__ biouh,
                const float* __restrict__ Wfx,   const float* __restrict__ bfx,
                const float* __restrict__ Wfh,   const float* __restrict__ bfh,
                const float* __restrict__ Wh,    const float* __restrict__ bh,
                const float* __restrict__ Wp,    const float* __restrict__ bp,
                float* __restrict__ out)
{
    __shared__ __align__(16) float s_f[16 * M];    // 16 KB
    __shared__ __align__(16) float s_fc[16 * M];   // 16 KB
    __shared__ int s_node[16], s_tok[16], s_parg[16], s_ptok[16];
    __shared__ int s_cs[16], s_ce[16];
    __shared__ int s_red[256];

    const int t   = threadIdx.x;
    const int gid = blockIdx.x * blockDim.x + threadIdx.x;
    const int gs  = gridDim.x * blockDim.x;
    const int G   = gridDim.x;

    // ------- Phase 0: zero counters + vocab projections -------------------
    {
        for (int i = gid; i < TOT; i += gs) { g_nchild[i] = 0; g_pend[i] = 0; }
        if (gid == 0) g_alloc = 0;

        const int VG = VOCAB / VNB;   // 125
        for (int g = blockIdx.x; g < VG; g += gridDim.x) {
            #pragma unroll
            for (int n = 0; n < VNB; n++)
                s_f[n * M + t] = emb[(g * VNB + n) * M + t];
            __syncthreads();
            float a0[VNB], a1[VNB], a2[VNB], af[VNB];
            #pragma unroll
            for (int n = 0; n < VNB; n++) {
                a0[n] = bioux[t]; a1[n] = bioux[M + t];
                a2[n] = bioux[2 * M + t]; af[n] = bfx[t];
            }
            #pragma unroll 1
            for (int k = 0; k < M; k += 4) {
                #pragma unroll
                for (int kk = 0; kk < 4; kk++) {
                    float w0 = Wioux[(k + kk) * M3 + t];
                    float w1 = Wioux[(k + kk) * M3 + M + t];
                    float w2 = Wioux[(k + kk) * M3 + 2 * M + t];
                    float wf = Wfx[(k + kk) * M + t];
                    #pragma unroll
                    for (int n = 0; n < VNB; n++) {
                        float xv = s_f[n * M + k + kk];
                        a0[n] += xv * w0; a1[n] += xv * w1;
                        a2[n] += xv * w2; af[n] += xv * wf;
                    }
                }
            }
            #pragma unroll
            for (int n = 0; n < VNB; n++) {
                int v = g * VNB + n;
                g_ioux[v * M3 + t]         = a0[n];
                g_ioux[v * M3 + M + t]     = a1[n];
                g_ioux[v * M3 + 2 * M + t] = a2[n];
                g_fxp[v * M + t]           = af[n];
            }
            __syncthreads();
        }
    }
    gsync();

    // loop-invariant biases
    const float bio0 = biouh[t], bio1 = biouh[M + t], bio2 = biouh[2 * M + t];
    const float bfh_t = bfh[t];

    // ------- Phase 1: child counts + leaf h/c tables ----------------------
    for (int i = gid; i < TOT; i += gs) {
        int tree = i >> 16, loc = i & (NNODE - 1);
        if (loc) {
            const int* parp = tree ? r_par : l_par;
            atomicAdd(&g_nchild[(tree << 16) + __ldg(parp + loc)], 1);
        }
    }
    for (int i = gid; i < VOCAB * M; i += gs) {
        int v = i / M, e = i % M;
        float i0 = g_ioux[v * M3 + e]         + biouh[e];
        float i1 = g_ioux[v * M3 + M + e]     + biouh[M + e];
        float i2 = g_ioux[v * M3 + 2 * M + e] + biouh[2 * M + e];
        float c  = sigf(i0) * tanhf(i2);
        g_cleaf[i] = c;
        g_hleaf[i] = sigf(i1) * tanhf(c);
    }
    gsync();

    // ------- Phase 2: pend counts + hfW table + scan part A ---------------
    for (int i = gid; i < TOT; i += gs) {
        int loc = i & (NNODE - 1);
        if (loc && __ldcg(&g_nchild[i]) > 0) {
            int tree = i >> 16;
            const int* parp = tree ? r_par : l_par;
            atomicAdd(&g_pend[(tree << 16) + __ldg(parp + loc)], 1);
        }
    }
    {
        const int VG = VOCAB / VNB;   // 125
        for (int g = blockIdx.x; g < VG; g += gridDim.x) {
            #pragma unroll
            for (int n = 0; n < VNB; n++)
                s_f[n * M + t] = g_hleaf[(g * VNB + n) * M + t];
            __syncthreads();
            float bf[VNB];
            #pragma unroll
            for (int n = 0; n < VNB; n++) bf[n] = bfh_t;
            #pragma unroll 1
            for (int k = 0; k < M; k += 4) {
                #pragma unroll
                for (int kk = 0; kk < 4; kk++) {
                    float w = Wfh[(k + kk) * M + t];
                    #pragma unroll
                    for (int n = 0; n < VNB; n++)
                        bf[n] += s_f[n * M + k + kk] * w;
                }
            }
            #pragma unroll
            for (int n = 0; n < VNB; n++)
                g_hfw[(g * VNB + n) * M + t] = bf[n];
            __syncthreads();
        }
    }
    {
        // per-block partial sum of nchild over its chunk
        const int chunk = (TOT + G - 1) / G;
        const int lo = blockIdx.x * chunk;
        const int hi = min(TOT, lo + chunk);
        int local = 0;
        for (int i = lo + t; i < hi; i += 256) local += __ldcg(&g_nchild[i]);
        s_red[t] = local;
        __syncthreads();
        for (int s = 128; s > 0; s >>= 1) {
            if (t < s) s_red[t] += s_red[t + s];
            __syncthreads();
        }
        if (t == 0) g_bsum[blockIdx.x] = s_red[0];
    }
    gsync();

    // ------- Phase 3: serial scan of block sums (tiny) --------------------
    if (blockIdx.x == 0 && t == 0) {
        int run = 0;
        for (int b = 0; b < G; b++) {
            int s = __ldcg(&g_bsum[b]);
            g_bsum[b] = run;
            run += s;
        }
    }
    gsync();

    // ------- Phase 4a: within-chunk exclusive scan (smem staged) ----------
    {
        const int chunk = (TOT + G - 1) / G;
        const int lo = blockIdx.x * chunk;
        const int hi = min(TOT, lo + chunk);
        int* s_i = reinterpret_cast<int*>(s_f);    // 4096 ints >= chunk
        for (int i = lo + t; i < hi; i += 256) s_i[i - lo] = __ldcg(&g_nchild[i]);
        __syncthreads();
        if (t == 0) {
            int run = __ldcg(&g_bsum[blockIdx.x]);
            for (int i = 0; i < hi - lo; i++) { int c = s_i[i]; s_i[i] = run; run += c; }
        }
        __syncthreads();
        for (int i = lo + t; i < hi; i += 256) {
            g_cstart[i] = s_i[i - lo];
            g_ccur[i]   = s_i[i - lo];
        }
    }
    gsync();

    // ------- Phase 4b: CSR fill + round-0 classify ------------------------
    for (int i = gid; i < TOT; i += gs) {
        int tree = i >> 16, loc = i & (NNODE - 1);
        if (loc) {
            const int* parp = tree ? r_par : l_par;
            const int* tokp = tree ? r_tok : l_tok;
            int pg = (tree << 16) + __ldg(parp + loc);
            int slot = atomicAdd(&g_ccur[pg], 1);
            int isleaf = (__ldcg(&g_nchild[i]) == 0);
            g_child[slot] = isleaf ? (int)(0x80000000u | (unsigned)tokp[loc]) : i;
        }
        if (__ldcg(&g_nchild[i]) > 0 && __ldcg(&g_pend[i]) == 0)
            g_order[atomicAdd(&g_alloc, 1)] = i;
    }
    gsync();   // snapshots g_alloc -> g_re (round 0 boundary)

    // ------- Phase 5: height-frontier round loop ---------------------------
    {
        int rs = 0;
        int re = __ldcg(&g_re);
        while (rs < re) {
            const int cnt = re - rs;
            // traffic-aware NT pick: cost = batches * max(fma, weights, floor)
            long best = 0x7fffffffffffL; int bestNT = 16;
            #pragma unroll
            for (int ntI = 0; ntI < 5; ntI++) {
                const int NTc = (ntI == 0) ? 16 : (ntI == 1) ? 8 : (ntI == 2) ? 4
                              : (ntI == 3) ? 2 : 1;
                int grp = (cnt + NTc - 1) / NTc;
                int bat = (grp + G - 1) / G;
                int gw  = grp < G ? grp : G;
                int wc  = NTc * 455;
                if (gw * 10 > wc) wc = gw * 10;
                if (wc < 250) wc = 250;
                long c = (long)bat * wc;
                if (c < best) { best = c; bestNT = NTc; }
            }
            if (bestNT == 16)
                do_round<16>(rs, cnt, l_tok, l_par, r_tok, r_par, Wiouh, Wfh,
                             bio0, bio1, bio2, bfh_t, s_f, s_fc,
                             s_node, s_tok, s_parg, s_ptok, s_cs, s_ce);
            else if (bestNT == 8)
                do_round<8>(rs, cnt, l_tok, l_par, r_tok, r_par, Wiouh, Wfh,
                            bio0, bio1, bio2, bfh_t, s_f, s_fc,
                            s_node, s_tok, s_parg, s_ptok, s_cs, s_ce);
            else if (bestNT == 4)
                do_round<4>(rs, cnt, l_tok, l_par, r_tok, r_par, Wiouh, Wfh,
                            bio0, bio1, bio2, bfh_t, s_f, s_fc,
                            s_node, s_tok, s_parg, s_ptok, s_cs, s_ce);
            else if (bestNT == 2)
                do_round<2>(rs, cnt, l_tok, l_par, r_tok, r_par, Wiouh, Wfh,
                            bio0, bio1, bio2, bfh_t, s_f, s_fc,
                            s_node, s_tok, s_parg, s_ptok, s_cs, s_ce);
            else
                do_round<1>(rs, cnt, l_tok, l_par, r_tok, r_par, Wiouh, Wfh,
                            bio0, bio1, bio2, bfh_t, s_f, s_fc,
                            s_node, s_tok, s_parg, s_ptok, s_cs, s_ce);
            gsync();                      // drains stores + snapshots next re
            rs = re;
            re = __ldcg(&g_re);
        }
    }

    // ------- Phase 6: similarity head (block 0) ----------------------------
    if (blockIdx.x == 0) {
        float cl = __ldcg(&g_croot[t]);
        float cr = __ldcg(&g_croot[M + t]);
        s_f[t]     = cl * cr;
        s_f[M + t] = fabsf(cl - cr);
        __syncthreads();
        float acc = bh[t];
        for (int k = 0; k < 2 * M; k++) acc += s_f[k] * Wh[k * M + t];
        float hid = sigf(acc);
        s_f[2 * M + t] = hid * Wp[2 * t];
        s_f[3 * M + t] = hid * Wp[2 * t + 1];
        __syncthreads();
        if (t == 0) {
            float l0 = bp[0], l1 = bp[1];
            for (int k = 0; k < M; k++) { l0 += s_f[2 * M + k]; l1 += s_f[3 * M + k]; }
            float mx = fmaxf(l0, l1);
            float e0 = expf(l0 - mx), e1 = expf(l1 - mx);
            float inv = 1.0f / (e0 + e1);
            out[0] = e0 * inv;
            out[1] = e1 * inv;
        }
    }
}

extern "C" void kernel_launch(void* const* d_in, const int* in_sizes, int n_in,
                              void* d_out, int out_size)
{
    (void)in_sizes; (void)n_in; (void)out_size;
    int dev = 0;
    cudaGetDevice(&dev);
    int nsm = 0;
    cudaDeviceGetAttribute(&nsm, cudaDevAttrMultiProcessorCount, dev);
    if (nsm <= 0) nsm = 148;

    treelstm_kernel<<<2 * nsm, 256>>>(
        (const int*)d_in[0], (const int*)d_in[1],
        (const int*)d_in[2], (const int*)d_in[3],
        (const float*)d_in[4],
        (const float*)d_in[5], (const float*)d_in[6],
        (const float*)d_in[7], (const float*)d_in[8],
        (const float*)d_in[9], (const float*)d_in[10],
        (const float*)d_in[11], (const float*)d_in[12],
        (const float*)d_in[13], (const float*)d_in[14],
        (const float*)d_in[15], (const float*)d_in[16],
        (float*)d_out);
}